// round 6
// baseline (speedup 1.0000x reference)
#include <cuda_runtime.h>
#include <cstdint>
#include <math.h>

#define HH 128
#define NPIX 16384
#define PI_F 3.14159265358979f

// Batch-independent per-pixel angle table (filled by init kernel each launch).
__device__ float g_theta[NPIX];

__global__ void init_theta_kernel() {
    int idx = blockIdx.x * blockDim.x + threadIdx.x;
    if (idx < NPIX) {
        float fi = (float)(idx >> 7) - 64.0f;   // xx - cx
        float fj = (float)(idx & 127) - 64.0f;  // yy - cy
        g_theta[idx] = atan2f(fj, fi);
    }
}

__device__ __forceinline__ float fast_sqrt(float x) {
    float r;
    asm("sqrt.approx.f32 %0, %1;" : "=f"(r) : "f"(x));
    return r;
}

#define CLUSTER_SYNC() do { \
    asm volatile("barrier.cluster.arrive.aligned;" ::: "memory"); \
    asm volatile("barrier.cluster.wait.aligned;" ::: "memory"); \
} while (0)

// 2-CTA cluster per image: each CTA computes 64 rows into a 32KB smem buffer,
// exchanges min/max with its peer over DSMEM, then normalizes its half.
// __launch_bounds__(256,5): 5 CTAs/SM (40 warps) -- the R4 kernel was RF-capped
// at 4 CTAs (64 regs); the dy recompute below frees the registers to fit 5.
__global__ void __launch_bounds__(256, 5) __cluster_dims__(2, 1, 1) decode_kernel(
    const float* __restrict__ W,
    const float* __restrict__ ng,
    const float* __restrict__ nu,
    float* __restrict__ out)
{
    __shared__ float img_s[8192];   // 64 rows x 128 cols
    __shared__ float s_sinx[128];
    __shared__ float s_yacc[128];
    __shared__ float s_g1[128];
    __shared__ float s_mi[128];
    __shared__ float s_pr[128];
    __shared__ float s_sind[256];
    __shared__ float s_red[24];

    const int b    = blockIdx.x >> 1;
    const int rank = blockIdx.x & 1;
    const int base = rank << 6;          // first row of this CTA's half
    const int t = threadIdx.x;

    const float* Wb = W + b * 16;
    float w0  = __ldg(Wb + 0),  w1  = __ldg(Wb + 1),  w2  = __ldg(Wb + 2),  w3  = __ldg(Wb + 3);
    float w4  = __ldg(Wb + 4),  w5  = __ldg(Wb + 5),  w6  = __ldg(Wb + 6),  w7  = __ldg(Wb + 7);
    float w8  = __ldg(Wb + 8),  w9  = __ldg(Wb + 9),  w10 = __ldg(Wb + 10), w11 = __ldg(Wb + 11);
    float w12 = __ldg(Wb + 12), w13 = __ldg(Wb + 13), w14 = __ldg(Wb + 14), w15 = __ldg(Wb + 15);

    // ---- per-image params ----
    const float c0  = w0 * 6.0f;
    float hf = floorf(fminf(fmaxf(__fadd_rn(__fmul_rn(fabsf(w1), 8.0f), 2.0f), 2.0f), 12.0f));
    const int lo_ = 64 - (int)hf;
    const int hi_ = 64 + (int)hf;
    const float kx = w2 * (2.0f * PI_F / 128.0f);
    const float ky = w3 * (2.0f * PI_F / 128.0f);
    const float kd = w4 * (PI_F / 256.0f);
    const float a5 = w5 * 10.0f;
    const float off = truncf(w7 * 5.0f);
    const float bxf = 64.0f + off;                 // bx == by
    const float sigma = 4.0f + fabsf(w7) * 5.0f;
    const float ninv = -0.5f / (sigma * sigma);
    const float rw8 = w8 * 10.0f;
    const float cb = floorf(fminf(fmaxf(__fadd_rn(__fmul_rn(fabsf(w9), 8.0f), 2.0f), 2.0f), 16.0f));
    const float invcb = 1.0f / cb;
    const float angle = w10 * PI_F;
    float sa, ca;
    sincosf(angle, &sa, &ca);
    const float k11 = w11 * 4.0f;
    const float k12 = 0.2f * w12;
    const float k13 = 0.2f * w13;

    // ---- fill 1-D tables ----
    if (t < 128) {
        float tt = (float)t;
        s_sinx[t] = 0.5f * sinf(kx * tt);
        float db = tt - bxf;
        s_g1[t] = expf(db * db * ninv);
        int ip = (int)floorf((tt + 0.5f) * invcb);  // == floor(t/cb) for integer t, integer cb
        s_mi[t] = (ip & 1) ? 0.15f : -0.15f;        // -0.15 * p_i
        s_pr[t] = (ip & 1) ? -1.0f : 1.0f;          // p_j
        s_yacc[t] = 0.5f * sinf(ky * tt)
                  + 0.5f * sinf((tt + a5) * (PI_F / 128.0f))
                  + w6
                  - 0.5f * k13
                  + 0.15f;                           // checkerboard constant folded in
    }
    s_sind[t] = 0.5f * sinf(kd * (float)t);
    __syncthreads();

    // ---- per-thread j-quad constants (register diet: dy terms recomputed in-loop) ----
    const int j0 = (t & 31) * 4;
    const float dyf = (float)(j0 - 64);
    float yaccl[4], gyl[4], sqh[4], pjl[4];
#pragma unroll
    for (int l = 0; l < 4; ++l) {
        int jl = j0 + l;
        yaccl[l] = s_yacc[jl];
        gyl[l]  = s_g1[jl];
        pjl[l]  = s_pr[jl];
        sqh[l]  = (jl >= lo_ && jl < hi_) ? 0.5f : 0.0f;
    }

    const int r0 = t >> 5;                       // warp id = local row within 8-row group
    const size_t gbase = (size_t)b * NPIX;
    const int pg0 = ((base + r0) << 7) + j0;     // first global pixel for this thread
    const float* ngp = ng + gbase + pg0;
    const float* nup = nu + gbase + pg0;
    const float* thp = g_theta + pg0;
    float* op = out + gbase + pg0;

    const float SQRT10 = 3.16227766016838f;

    float mnv = __int_as_float(0x7f800000);
    float mxv = __int_as_float(0xff800000);

    // ---- pass 1: compute 64 rows into smem, track min/max ----
#pragma unroll 2
    for (int k = 0; k < 8; ++k) {
        const int q = k << 10;                   // k * 8 rows * 128
        const float4 g4 = __ldcs((const float4*)(ngp + q));
        const float4 u4 = __ldcs((const float4*)(nup + q));
        const float4 th4 = *(const float4*)(thp + q);

        const int i = base + r0 + (k << 3);      // global row
        const float dx = (float)i - 64.0f;
        const float dx2 = dx * dx;
        const float sinxi = s_sinx[i];
        const float g1i = s_g1[i];
        const float mi_i = s_mi[i];
        const float xm = (i >= lo_ && i < hi_) ? 1.0f : 0.0f;
        const float cadx = ca * dx;
        const int sb = i + j0;

        float gq[4] = {g4.x, g4.y, g4.z, g4.w};
        float uq[4] = {u4.x, u4.y, u4.z, u4.w};
        float thq[4] = {th4.x, th4.y, th4.z, th4.w};
        float v[4];
#pragma unroll
        for (int l = 0; l < 4; ++l) {
            const float dl = dyf + (float)l;                       // FADD-imm (replaces dy2c/sady regs)
            float r = fast_sqrt(fmaf(dl, dl, dx2));
            float val = yaccl[l] + __saturatef(c0 - r);            // disk
            val = fmaf(xm, sqh[l], val);                           // central square
            val += sinxi;                                          // x-sinusoid
            val += s_sind[sb + l];                                 // diagonal sinusoid
            val = fmaf(g1i, gyl[l], val);                          // gaussian (separable)
            if (fabsf(r - rw8) < SQRT10) val += 1.0f;              // ring
            val = fmaf(mi_i, pjl[l], val);                         // checkerboard
            if (fabsf(fmaf(sa, dl, cadx)) < 3.0f) val += 0.6f;     // rotated line
            val = fmaf(0.5f, __sinf(thq[l] * k11), val);           // angular sinusoid
            val = fmaf(gq[l], k12, val);                           // gaussian noise
            val = fmaf(uq[l], k13, val);                           // uniform noise
            v[l] = val;
        }
        mnv = fminf(mnv, fminf(fminf(v[0], v[1]), fminf(v[2], v[3])));
        mxv = fmaxf(mxv, fmaxf(fmaxf(v[0], v[1]), fmaxf(v[2], v[3])));
        *(float4*)(img_s + ((r0 + (k << 3)) << 7) + j0) = make_float4(v[0], v[1], v[2], v[3]);
    }

    // ---- local (half-image) min/max reduction ----
#pragma unroll
    for (int o = 16; o; o >>= 1) {
        mnv = fminf(mnv, __shfl_xor_sync(0xffffffffu, mnv, o));
        mxv = fmaxf(mxv, __shfl_xor_sync(0xffffffffu, mxv, o));
    }
    if ((t & 31) == 0) {
        s_red[t >> 5] = mnv;
        s_red[8 + (t >> 5)] = mxv;
    }
    __syncthreads();
    if (t == 0) {
        float gmn = s_red[0], gmx = s_red[8];
#pragma unroll
        for (int wdx = 1; wdx < 8; ++wdx) {
            gmn = fminf(gmn, s_red[wdx]);
            gmx = fmaxf(gmx, s_red[8 + wdx]);
        }
        s_red[16] = gmn;
        s_red[17] = gmx;
    }

    // ---- cluster exchange: combine halves ----
    CLUSTER_SYNC();   // release s_red[16..17] to peer; all cluster threads arrive
    if (t == 0) {
        unsigned int laddr = (unsigned int)__cvta_generic_to_shared(&s_red[16]);
        unsigned int paddr;
        unsigned int peer = (unsigned int)(rank ^ 1);
        asm("mapa.shared::cluster.u32 %0, %1, %2;" : "=r"(paddr) : "r"(laddr), "r"(peer));
        float pmn, pmx;
        asm("ld.shared::cluster.f32 %0, [%1];"   : "=f"(pmn) : "r"(paddr));
        asm("ld.shared::cluster.f32 %0, [%1+4];" : "=f"(pmx) : "r"(paddr));
        float gmn = fminf(s_red[16], pmn);
        float gmx = fmaxf(s_red[17], pmx);
        // fold contrast, inversion, min/max normalization into out = (x - x0) * A
        float c = 1.0f + w14;
        float pp = (w15 > 0.0f) ? -c : c;
        float ap = fabsf(pp);
        float denom = (gmx - gmn) + 1e-8f / ap;    // ap==0 -> inf -> A=0 -> out=0 (matches ref)
        float A = ((pp > 0.0f) ? 1.0f : -1.0f) / denom;
        float x0 = (pp > 0.0f) ? gmn : gmx;
        s_red[18] = A;
        s_red[19] = x0;
    }
    CLUSTER_SYNC();   // peer done reading our [16,17]; our threads see [18,19]

    const float A = s_red[18];
    const float C = -s_red[19] * A;

    // ---- pass 2: normalize from smem, store final ----
#pragma unroll 4
    for (int k = 0; k < 8; ++k) {
        const int q = k << 10;
        float4 vv = *(const float4*)(img_s + ((r0 + (k << 3)) << 7) + j0);
        vv.x = fmaf(vv.x, A, C);
        vv.y = fmaf(vv.y, A, C);
        vv.z = fmaf(vv.z, A, C);
        vv.w = fmaf(vv.w, A, C);
        *(float4*)(op + q) = vv;
    }
}

extern "C" void kernel_launch(void* const* d_in, const int* in_sizes, int n_in,
                              void* d_out, int out_size) {
    const float* W  = (const float*)d_in[0];   // (2048, 16)
    const float* ng = (const float*)d_in[1];   // (2048, 128, 128)
    const float* nu = (const float*)d_in[2];   // (2048, 128, 128)
    float* out = (float*)d_out;                // (2048, 1, 128, 128)

    (void)in_sizes; (void)n_in; (void)out_size;

    init_theta_kernel<<<NPIX / 256, 256>>>();
    decode_kernel<<<4096, 256>>>(W, ng, nu, out);
}

// round 7
// speedup vs baseline: 1.0073x; 1.0073x over previous
#include <cuda_runtime.h>
#include <cstdint>
#include <math.h>

#define HH 128
#define NPIX 16384
#define PI_F 3.14159265358979f

// Batch-independent per-pixel angle table (filled by init kernel each launch).
__device__ float g_theta[NPIX];

__global__ void init_theta_kernel() {
    int idx = blockIdx.x * blockDim.x + threadIdx.x;
    if (idx < NPIX) {
        float fi = (float)(idx >> 7) - 64.0f;   // xx - cx
        float fj = (float)(idx & 127) - 64.0f;  // yy - cy
        g_theta[idx] = atan2f(fj, fi);
    }
}

__device__ __forceinline__ float fast_sqrt(float x) {
    float r;
    asm("sqrt.approx.f32 %0, %1;" : "=f"(r) : "f"(x));
    return r;
}

#define CLUSTER_SYNC() do { \
    asm volatile("barrier.cluster.arrive.aligned;" ::: "memory"); \
    asm volatile("barrier.cluster.wait.aligned;" ::: "memory"); \
} while (0)

// 2-CTA cluster per image, 4 CTAs/SM (R4-best config). Diagonal sinusoid computed
// via angle-addition (2 FMA + broadcast LDS) instead of a stride-4 scalar LDS that
// had a 4-way bank conflict on every pixel.
__global__ void __launch_bounds__(256, 4) __cluster_dims__(2, 1, 1) decode_kernel(
    const float* __restrict__ W,
    const float* __restrict__ ng,
    const float* __restrict__ nu,
    float* __restrict__ out)
{
    __shared__ float img_s[8192];   // 64 rows x 128 cols
    __shared__ float s_sinx[128];
    __shared__ float s_yacc[128];
    __shared__ float s_g1[128];
    __shared__ float s_mi[128];
    __shared__ float s_pr[128];
    __shared__ float s_sd[128];     // sin(kd * t)
    __shared__ float s_cd[128];     // cos(kd * t)
    __shared__ float s_red[24];

    const int b    = blockIdx.x >> 1;
    const int rank = blockIdx.x & 1;
    const int base = rank << 6;          // first row of this CTA's half
    const int t = threadIdx.x;

    const float* Wb = W + b * 16;
    float w0  = __ldg(Wb + 0),  w1  = __ldg(Wb + 1),  w2  = __ldg(Wb + 2),  w3  = __ldg(Wb + 3);
    float w4  = __ldg(Wb + 4),  w5  = __ldg(Wb + 5),  w6  = __ldg(Wb + 6),  w7  = __ldg(Wb + 7);
    float w8  = __ldg(Wb + 8),  w9  = __ldg(Wb + 9),  w10 = __ldg(Wb + 10), w11 = __ldg(Wb + 11);
    float w12 = __ldg(Wb + 12), w13 = __ldg(Wb + 13), w14 = __ldg(Wb + 14), w15 = __ldg(Wb + 15);

    // ---- per-image params ----
    const float c0  = w0 * 6.0f;
    float hf = floorf(fminf(fmaxf(__fadd_rn(__fmul_rn(fabsf(w1), 8.0f), 2.0f), 2.0f), 12.0f));
    const int lo_ = 64 - (int)hf;
    const int hi_ = 64 + (int)hf;
    const float kx = w2 * (2.0f * PI_F / 128.0f);
    const float ky = w3 * (2.0f * PI_F / 128.0f);
    const float kd = w4 * (PI_F / 256.0f);
    const float a5 = w5 * 10.0f;
    const float off = truncf(w7 * 5.0f);
    const float bxf = 64.0f + off;                 // bx == by
    const float sigma = 4.0f + fabsf(w7) * 5.0f;
    const float ninv = -0.5f / (sigma * sigma);
    const float rw8 = w8 * 10.0f;
    const float cb = floorf(fminf(fmaxf(__fadd_rn(__fmul_rn(fabsf(w9), 8.0f), 2.0f), 2.0f), 16.0f));
    const float invcb = 1.0f / cb;
    const float angle = w10 * PI_F;
    float sa, ca;
    sincosf(angle, &sa, &ca);
    const float k11 = w11 * 4.0f;
    const float k12 = 0.2f * w12;
    const float k13 = 0.2f * w13;

    // ---- fill 1-D tables ----
    if (t < 128) {
        float tt = (float)t;
        s_sinx[t] = 0.5f * sinf(kx * tt);
        float db = tt - bxf;
        s_g1[t] = expf(db * db * ninv);
        int ip = (int)floorf((tt + 0.5f) * invcb);  // == floor(t/cb) for integer t, integer cb
        s_mi[t] = (ip & 1) ? 0.15f : -0.15f;        // -0.15 * p_i
        s_pr[t] = (ip & 1) ? -1.0f : 1.0f;          // p_j
        float sd, cd;
        sincosf(kd * tt, &sd, &cd);
        s_sd[t] = sd;
        s_cd[t] = cd;
        s_yacc[t] = 0.5f * sinf(ky * tt)
                  + 0.5f * sinf((tt + a5) * (PI_F / 128.0f))
                  + w6
                  - 0.5f * k13
                  + 0.15f;                           // checkerboard constant folded in
    }
    __syncthreads();

    // ---- per-thread j-quad constants ----
    const int j0 = (t & 31) * 4;
    const float dyf = (float)(j0 - 64);
    float yaccl[4], gyl[4], sqh[4], pjl[4], sdjh[4], cdjh[4];
#pragma unroll
    for (int l = 0; l < 4; ++l) {
        int jl = j0 + l;
        yaccl[l] = s_yacc[jl];
        gyl[l]  = s_g1[jl];
        pjl[l]  = s_pr[jl];
        sdjh[l] = 0.5f * s_sd[jl];                   // 0.5*sin(kd*j)
        cdjh[l] = 0.5f * s_cd[jl];                   // 0.5*cos(kd*j)
        sqh[l]  = (jl >= lo_ && jl < hi_) ? 0.5f : 0.0f;
    }

    const int r0 = t >> 5;                       // warp id = local row within 8-row group
    const size_t gbase = (size_t)b * NPIX;
    const int pg0 = ((base + r0) << 7) + j0;     // first global pixel for this thread
    const float* ngp = ng + gbase + pg0;
    const float* nup = nu + gbase + pg0;
    const float* thp = g_theta + pg0;
    float* op = out + gbase + pg0;

    const float SQRT10 = 3.16227766016838f;

    float mnv = __int_as_float(0x7f800000);
    float mxv = __int_as_float(0xff800000);

    // ---- pass 1: compute 64 rows into smem, track min/max ----
#pragma unroll 2
    for (int k = 0; k < 8; ++k) {
        const int q = k << 10;                   // k * 8 rows * 128
        const float4 g4 = __ldcs((const float4*)(ngp + q));
        const float4 u4 = __ldcs((const float4*)(nup + q));
        const float4 th4 = *(const float4*)(thp + q);

        const int i = base + r0 + (k << 3);      // global row
        const float dx = (float)i - 64.0f;
        const float dx2 = dx * dx;
        const float sinxi = s_sinx[i];
        const float g1i = s_g1[i];
        const float mi_i = s_mi[i];
        const float sdi = s_sd[i];               // broadcast, conflict-free
        const float cdi = s_cd[i];
        const float xm = (i >= lo_ && i < hi_) ? 1.0f : 0.0f;
        const float cadx = ca * dx;

        float gq[4] = {g4.x, g4.y, g4.z, g4.w};
        float uq[4] = {u4.x, u4.y, u4.z, u4.w};
        float thq[4] = {th4.x, th4.y, th4.z, th4.w};
        float v[4];
#pragma unroll
        for (int l = 0; l < 4; ++l) {
            const float dl = dyf + (float)l;
            float r = fast_sqrt(fmaf(dl, dl, dx2));
            float val = yaccl[l] + __saturatef(c0 - r);            // disk
            val = fmaf(xm, sqh[l], val);                           // central square
            val += sinxi;                                          // x-sinusoid
            val = fmaf(sdi, cdjh[l], val);                         // diag sin: 0.5*sin(kd(i+j))
            val = fmaf(cdi, sdjh[l], val);                         //   via angle addition
            val = fmaf(g1i, gyl[l], val);                          // gaussian (separable)
            if (fabsf(r - rw8) < SQRT10) val += 1.0f;              // ring
            val = fmaf(mi_i, pjl[l], val);                         // checkerboard
            if (fabsf(fmaf(sa, dl, cadx)) < 3.0f) val += 0.6f;     // rotated line
            val = fmaf(0.5f, __sinf(thq[l] * k11), val);           // angular sinusoid
            val = fmaf(gq[l], k12, val);                           // gaussian noise
            val = fmaf(uq[l], k13, val);                           // uniform noise
            v[l] = val;
        }
        mnv = fminf(mnv, fminf(fminf(v[0], v[1]), fminf(v[2], v[3])));
        mxv = fmaxf(mxv, fmaxf(fmaxf(v[0], v[1]), fmaxf(v[2], v[3])));
        *(float4*)(img_s + ((r0 + (k << 3)) << 7) + j0) = make_float4(v[0], v[1], v[2], v[3]);
    }

    // ---- local (half-image) min/max reduction ----
#pragma unroll
    for (int o = 16; o; o >>= 1) {
        mnv = fminf(mnv, __shfl_xor_sync(0xffffffffu, mnv, o));
        mxv = fmaxf(mxv, __shfl_xor_sync(0xffffffffu, mxv, o));
    }
    if ((t & 31) == 0) {
        s_red[t >> 5] = mnv;
        s_red[8 + (t >> 5)] = mxv;
    }
    __syncthreads();
    if (t == 0) {
        float gmn = s_red[0], gmx = s_red[8];
#pragma unroll
        for (int wdx = 1; wdx < 8; ++wdx) {
            gmn = fminf(gmn, s_red[wdx]);
            gmx = fmaxf(gmx, s_red[8 + wdx]);
        }
        s_red[16] = gmn;
        s_red[17] = gmx;
    }

    // ---- cluster exchange: combine halves ----
    CLUSTER_SYNC();   // release s_red[16..17] to peer; all cluster threads arrive
    if (t == 0) {
        unsigned int laddr = (unsigned int)__cvta_generic_to_shared(&s_red[16]);
        unsigned int paddr;
        unsigned int peer = (unsigned int)(rank ^ 1);
        asm("mapa.shared::cluster.u32 %0, %1, %2;" : "=r"(paddr) : "r"(laddr), "r"(peer));
        float pmn, pmx;
        asm("ld.shared::cluster.f32 %0, [%1];"   : "=f"(pmn) : "r"(paddr));
        asm("ld.shared::cluster.f32 %0, [%1+4];" : "=f"(pmx) : "r"(paddr));
        float gmn = fminf(s_red[16], pmn);
        float gmx = fmaxf(s_red[17], pmx);
        // fold contrast, inversion, min/max normalization into out = (x - x0) * A
        float c = 1.0f + w14;
        float pp = (w15 > 0.0f) ? -c : c;
        float ap = fabsf(pp);
        float denom = (gmx - gmn) + 1e-8f / ap;    // ap==0 -> inf -> A=0 -> out=0 (matches ref)
        float A = ((pp > 0.0f) ? 1.0f : -1.0f) / denom;
        float x0 = (pp > 0.0f) ? gmn : gmx;
        s_red[18] = A;
        s_red[19] = x0;
    }
    CLUSTER_SYNC();   // peer done reading our [16,17]; our threads see [18,19]

    const float A = s_red[18];
    const float C = -s_red[19] * A;

    // ---- pass 2: normalize from smem, store final ----
#pragma unroll 4
    for (int k = 0; k < 8; ++k) {
        const int q = k << 10;
        float4 vv = *(const float4*)(img_s + ((r0 + (k << 3)) << 7) + j0);
        vv.x = fmaf(vv.x, A, C);
        vv.y = fmaf(vv.y, A, C);
        vv.z = fmaf(vv.z, A, C);
        vv.w = fmaf(vv.w, A, C);
        *(float4*)(op + q) = vv;
    }
}

extern "C" void kernel_launch(void* const* d_in, const int* in_sizes, int n_in,
                              void* d_out, int out_size) {
    const float* W  = (const float*)d_in[0];   // (2048, 16)
    const float* ng = (const float*)d_in[1];   // (2048, 128, 128)
    const float* nu = (const float*)d_in[2];   // (2048, 128, 128)
    float* out = (float*)d_out;                // (2048, 1, 128, 128)

    (void)in_sizes; (void)n_in; (void)out_size;

    init_theta_kernel<<<NPIX / 256, 256>>>();
    decode_kernel<<<4096, 256>>>(W, ng, nu, out);
}

// round 8
// speedup vs baseline: 1.1826x; 1.1740x over previous
#include <cuda_runtime.h>
#include <cstdint>
#include <math.h>

#define HH 128
#define NPIX 16384
#define PI_F 3.14159265358979f

// Batch-independent per-pixel angle table (filled by init kernel each launch).
__device__ float g_theta[NPIX];

__global__ void init_theta_kernel() {
    int idx = blockIdx.x * blockDim.x + threadIdx.x;
    if (idx < NPIX) {
        float fi = (float)(idx >> 7) - 64.0f;   // xx - cx
        float fj = (float)(idx & 127) - 64.0f;  // yy - cy
        g_theta[idx] = atan2f(fj, fi);
    }
}

__device__ __forceinline__ float fast_sqrt(float x) {
    float r;
    asm("sqrt.approx.f32 %0, %1;" : "=f"(r) : "f"(x));
    return r;
}

__device__ __forceinline__ void cp16(float* dst_smem, const float* src) {
    unsigned int a = (unsigned int)__cvta_generic_to_shared(dst_smem);
    asm volatile("cp.async.cg.shared.global [%0], [%1], 16;" :: "r"(a), "l"(src) : "memory");
}
#define CP_COMMIT() asm volatile("cp.async.commit_group;" ::: "memory")

#define CLUSTER_SYNC() do { \
    asm volatile("barrier.cluster.arrive.aligned;" ::: "memory"); \
    asm volatile("barrier.cluster.wait.aligned;" ::: "memory"); \
} while (0)

// 2-CTA cluster per image, 4 CTAs/SM. Noise streams are staged through a
// 2-deep cp.async smem ring (per-thread producer==consumer, so only
// cp.async.wait_group is needed -- no barriers in pass 1). This removes the
// per-iteration LDG long-scoreboard dependency that capped issue at ~52%.
__global__ void __launch_bounds__(256, 4) __cluster_dims__(2, 1, 1) decode_kernel(
    const float* __restrict__ W,
    const float* __restrict__ ng,
    const float* __restrict__ nu,
    float* __restrict__ out)
{
    __shared__ float img_s[8192];           // 64 rows x 128 cols
    __shared__ float s_nbuf[2][2][1024];    // [stage buf][0=ng,1=nu][8 rows x 128]
    __shared__ float s_sinx[128];
    __shared__ float s_yacc[128];
    __shared__ float s_g1[128];
    __shared__ float s_mi[128];
    __shared__ float s_pr[128];
    __shared__ float s_sind[256];
    __shared__ float s_red[24];

    const int b    = blockIdx.x >> 1;
    const int rank = blockIdx.x & 1;
    const int base = rank << 6;          // first row of this CTA's half
    const int t = threadIdx.x;
    const int t4 = t << 2;               // this thread's float offset within a stage

    const size_t gbase = (size_t)b * NPIX;
    const float* ngc = ng + gbase + (base << 7);   // CTA-half base
    const float* nuc = nu + gbase + (base << 7);

    // ---- prologue: start stages 0 and 1 of the noise pipeline immediately ----
    cp16(&s_nbuf[0][0][t4], ngc + t4);
    cp16(&s_nbuf[0][1][t4], nuc + t4);
    CP_COMMIT();
    cp16(&s_nbuf[1][0][t4], ngc + 1024 + t4);
    cp16(&s_nbuf[1][1][t4], nuc + 1024 + t4);
    CP_COMMIT();

    const float* Wb = W + b * 16;
    float w0  = __ldg(Wb + 0),  w1  = __ldg(Wb + 1),  w2  = __ldg(Wb + 2),  w3  = __ldg(Wb + 3);
    float w4  = __ldg(Wb + 4),  w5  = __ldg(Wb + 5),  w6  = __ldg(Wb + 6),  w7  = __ldg(Wb + 7);
    float w8  = __ldg(Wb + 8),  w9  = __ldg(Wb + 9),  w10 = __ldg(Wb + 10), w11 = __ldg(Wb + 11);
    float w12 = __ldg(Wb + 12), w13 = __ldg(Wb + 13), w14 = __ldg(Wb + 14), w15 = __ldg(Wb + 15);

    // ---- per-image params ----
    const float c0  = w0 * 6.0f;
    float hf = floorf(fminf(fmaxf(__fadd_rn(__fmul_rn(fabsf(w1), 8.0f), 2.0f), 2.0f), 12.0f));
    const int lo_ = 64 - (int)hf;
    const int hi_ = 64 + (int)hf;
    const float kx = w2 * (2.0f * PI_F / 128.0f);
    const float ky = w3 * (2.0f * PI_F / 128.0f);
    const float kd = w4 * (PI_F / 256.0f);
    const float a5 = w5 * 10.0f;
    const float off = truncf(w7 * 5.0f);
    const float bxf = 64.0f + off;                 // bx == by
    const float sigma = 4.0f + fabsf(w7) * 5.0f;
    const float ninv = -0.5f / (sigma * sigma);
    const float rw8 = w8 * 10.0f;
    const float cb = floorf(fminf(fmaxf(__fadd_rn(__fmul_rn(fabsf(w9), 8.0f), 2.0f), 2.0f), 16.0f));
    const float invcb = 1.0f / cb;
    const float angle = w10 * PI_F;
    float sa, ca;
    sincosf(angle, &sa, &ca);
    const float k11 = w11 * 4.0f;
    const float k12 = 0.2f * w12;
    const float k13 = 0.2f * w13;

    // ---- fill 1-D tables ----
    if (t < 128) {
        float tt = (float)t;
        s_sinx[t] = 0.5f * sinf(kx * tt);
        float db = tt - bxf;
        s_g1[t] = expf(db * db * ninv);
        int ip = (int)floorf((tt + 0.5f) * invcb);  // == floor(t/cb) for integer t, integer cb
        s_mi[t] = (ip & 1) ? 0.15f : -0.15f;        // -0.15 * p_i
        s_pr[t] = (ip & 1) ? -1.0f : 1.0f;          // p_j
        s_yacc[t] = 0.5f * sinf(ky * tt)
                  + 0.5f * sinf((tt + a5) * (PI_F / 128.0f))
                  + w6
                  - 0.5f * k13
                  + 0.15f;                           // checkerboard constant folded in
    }
    s_sind[t] = 0.5f * sinf(kd * (float)t);
    __syncthreads();

    // ---- per-thread j-quad constants ----
    const int j0 = (t & 31) * 4;
    const float dyf = (float)(j0 - 64);
    float yaccl[4], gyl[4], sqh[4], pjl[4];
#pragma unroll
    for (int l = 0; l < 4; ++l) {
        int jl = j0 + l;
        yaccl[l] = s_yacc[jl];
        gyl[l]  = s_g1[jl];
        pjl[l]  = s_pr[jl];
        sqh[l]  = (jl >= lo_ && jl < hi_) ? 0.5f : 0.0f;
    }

    const int r0 = t >> 5;                       // warp id = local row within 8-row group
    const int pg0 = ((base + r0) << 7) + j0;     // first global pixel for this thread
    const float* thp = g_theta + pg0;
    float* op = out + gbase + pg0;

    const float SQRT10 = 3.16227766016838f;

    float mnv = __int_as_float(0x7f800000);
    float mxv = __int_as_float(0xff800000);

    // theta prefetch (L2-resident table)
    float4 th4 = *(const float4*)(thp);

    // ---- pass 1: compute 64 rows into smem, cp.async-pipelined noise ----
#pragma unroll
    for (int k = 0; k < 8; ++k) {
        // wait for stage k (leave the newer in-flight group pending)
        if (k < 7) asm volatile("cp.async.wait_group 1;" ::: "memory");
        else       asm volatile("cp.async.wait_group 0;" ::: "memory");

        // consume my 16B of each stage buffer
        const float4 g4 = *(const float4*)&s_nbuf[k & 1][0][t4];
        const float4 u4 = *(const float4*)&s_nbuf[k & 1][1][t4];

        // refill this buffer with stage k+2
        if (k < 6) {
            const int qn = (k + 2) << 10;
            cp16(&s_nbuf[k & 1][0][t4], ngc + qn + t4);
            cp16(&s_nbuf[k & 1][1][t4], nuc + qn + t4);
            CP_COMMIT();
        }

        const float4 tc = th4;
        if (k < 7) th4 = *(const float4*)(thp + ((k + 1) << 10));

        const int i = base + r0 + (k << 3);      // global row
        const float dx = (float)i - 64.0f;
        const float dx2 = dx * dx;
        const float sinxi = s_sinx[i];
        const float g1i = s_g1[i];
        const float mi_i = s_mi[i];
        const float xm = (i >= lo_ && i < hi_) ? 1.0f : 0.0f;
        const float cadx = ca * dx;
        const int sb = i + j0;

        float gq[4] = {g4.x, g4.y, g4.z, g4.w};
        float uq[4] = {u4.x, u4.y, u4.z, u4.w};
        float thq[4] = {tc.x, tc.y, tc.z, tc.w};
        float v[4];
#pragma unroll
        for (int l = 0; l < 4; ++l) {
            const float dl = dyf + (float)l;
            float r = fast_sqrt(fmaf(dl, dl, dx2));
            float val = yaccl[l] + __saturatef(c0 - r);            // disk
            val = fmaf(xm, sqh[l], val);                           // central square
            val += sinxi;                                          // x-sinusoid
            val += s_sind[sb + l];                                 // diagonal sinusoid
            val = fmaf(g1i, gyl[l], val);                          // gaussian (separable)
            if (fabsf(r - rw8) < SQRT10) val += 1.0f;              // ring
            val = fmaf(mi_i, pjl[l], val);                         // checkerboard
            if (fabsf(fmaf(sa, dl, cadx)) < 3.0f) val += 0.6f;     // rotated line
            val = fmaf(0.5f, __sinf(thq[l] * k11), val);           // angular sinusoid
            val = fmaf(gq[l], k12, val);                           // gaussian noise
            val = fmaf(uq[l], k13, val);                           // uniform noise
            v[l] = val;
        }
        mnv = fminf(mnv, fminf(fminf(v[0], v[1]), fminf(v[2], v[3])));
        mxv = fmaxf(mxv, fmaxf(fmaxf(v[0], v[1]), fmaxf(v[2], v[3])));
        *(float4*)(img_s + ((r0 + (k << 3)) << 7) + j0) = make_float4(v[0], v[1], v[2], v[3]);
    }

    // ---- local (half-image) min/max reduction ----
#pragma unroll
    for (int o = 16; o; o >>= 1) {
        mnv = fminf(mnv, __shfl_xor_sync(0xffffffffu, mnv, o));
        mxv = fmaxf(mxv, __shfl_xor_sync(0xffffffffu, mxv, o));
    }
    if ((t & 31) == 0) {
        s_red[t >> 5] = mnv;
        s_red[8 + (t >> 5)] = mxv;
    }
    __syncthreads();
    if (t == 0) {
        float gmn = s_red[0], gmx = s_red[8];
#pragma unroll
        for (int wdx = 1; wdx < 8; ++wdx) {
            gmn = fminf(gmn, s_red[wdx]);
            gmx = fmaxf(gmx, s_red[8 + wdx]);
        }
        s_red[16] = gmn;
        s_red[17] = gmx;
    }

    // ---- cluster exchange: combine halves ----
    CLUSTER_SYNC();   // release s_red[16..17] to peer; all cluster threads arrive
    if (t == 0) {
        unsigned int laddr = (unsigned int)__cvta_generic_to_shared(&s_red[16]);
        unsigned int paddr;
        unsigned int peer = (unsigned int)(rank ^ 1);
        asm("mapa.shared::cluster.u32 %0, %1, %2;" : "=r"(paddr) : "r"(laddr), "r"(peer));
        float pmn, pmx;
        asm("ld.shared::cluster.f32 %0, [%1];"   : "=f"(pmn) : "r"(paddr));
        asm("ld.shared::cluster.f32 %0, [%1+4];" : "=f"(pmx) : "r"(paddr));
        float gmn = fminf(s_red[16], pmn);
        float gmx = fmaxf(s_red[17], pmx);
        // fold contrast, inversion, min/max normalization into out = (x - x0) * A
        float c = 1.0f + w14;
        float pp = (w15 > 0.0f) ? -c : c;
        float ap = fabsf(pp);
        float denom = (gmx - gmn) + 1e-8f / ap;    // ap==0 -> inf -> A=0 -> out=0 (matches ref)
        float A = ((pp > 0.0f) ? 1.0f : -1.0f) / denom;
        float x0 = (pp > 0.0f) ? gmn : gmx;
        s_red[18] = A;
        s_red[19] = x0;
    }
    CLUSTER_SYNC();   // peer done reading our [16,17]; our threads see [18,19]

    const float A = s_red[18];
    const float C = -s_red[19] * A;

    // ---- pass 2: normalize from smem, store final ----
#pragma unroll 4
    for (int k = 0; k < 8; ++k) {
        const int q = k << 10;
        float4 vv = *(const float4*)(img_s + ((r0 + (k << 3)) << 7) + j0);
        vv.x = fmaf(vv.x, A, C);
        vv.y = fmaf(vv.y, A, C);
        vv.z = fmaf(vv.z, A, C);
        vv.w = fmaf(vv.w, A, C);
        *(float4*)(op + q) = vv;
    }
}

extern "C" void kernel_launch(void* const* d_in, const int* in_sizes, int n_in,
                              void* d_out, int out_size) {
    const float* W  = (const float*)d_in[0];   // (2048, 16)
    const float* ng = (const float*)d_in[1];   // (2048, 128, 128)
    const float* nu = (const float*)d_in[2];   // (2048, 128, 128)
    float* out = (float*)d_out;                // (2048, 1, 128, 128)

    (void)in_sizes; (void)n_in; (void)out_size;

    init_theta_kernel<<<NPIX / 256, 256>>>();
    decode_kernel<<<4096, 256>>>(W, ng, nu, out);
}